// round 4
// baseline (speedup 1.0000x reference)
#include <cuda_runtime.h>

#define BB 32
#define TT_IN 1024
#define TP 1025
#define EMB 384
#define GC 96
#define NWARPS 12
#define NKS 36            // K-steps per group: 3 kk * 96 ch / 8
#define NCHUNK 5
#define SUBS 13           // m16-subtiles per chunk (5*13*16 = 1040 >= 1025)
#define XS_PAD 100        // padded row stride (floats) -> conflict-free frags

// Scratch (device globals: no allocations allowed)
__device__ int          g_cum[BB * TP];
__device__ unsigned int g_wB[4 * NWARPS * NKS * 2 * 32];  // tf32 B fragments
__device__ float        g_part[4 * BB * TP];              // per-group pred partials

#define CVT_TF32(u, f) asm("cvt.rna.tf32.f32 %0, %1;" : "=r"(u) : "f"(f))

#define MMA_TF32(d0,d1,d2,d3, a0,a1,a2,a3, b0,b1)                          \
    asm("mma.sync.aligned.m16n8k8.row.col.f32.tf32.tf32.f32 "              \
        "{%0,%1,%2,%3}, {%4,%5,%6,%7}, {%8,%9}, {%0,%1,%2,%3};"            \
        : "+f"(d0), "+f"(d1), "+f"(d2), "+f"(d3)                           \
        : "r"(a0), "r"(a1), "r"(a2), "r"(a3), "r"(b0), "r"(b1))

// ---------------------------------------------------------------------------
// Pre-pack conv1 weights into tf32 mma B-fragment order:
// g_wB[g][nt][ks][r][lane] ; b_r value = W[k = ks*8 + (lane&3) + 4r][n],
// n = nt*8 + lane/4, where K order is k = kk*96 + i  (kk = ks/12).
// ---------------------------------------------------------------------------
__global__ void prep_w_kernel(const float* __restrict__ w1) {
    int t = blockIdx.x * blockDim.x + threadIdx.x;
    if (t >= 4 * NWARPS * NKS * 32) return;
    int lane = t & 31;
    int rest = t >> 5;
    int ks = rest % NKS;
    int nt = (rest / NKS) % NWARPS;
    int g  = rest / (NKS * NWARPS);

    int kk = ks / 12;
    int n  = nt * 8 + (lane >> 2);
    int C  = g * GC + n;
#pragma unroll
    for (int r = 0; r < 2; r++) {
        int i = (ks % 12) * 8 + (lane & 3) + 4 * r;
        float w = w1[C * (GC * 3) + i * 3 + kk];
        unsigned u; CVT_TF32(u, w);
        g_wB[(((g * NWARPS + nt) * NKS + ks) * 2 + r) * 32 + lane] = u;
    }
}

// ---------------------------------------------------------------------------
// Inclusive cumsum of durations per batch row (one block per b)
// ---------------------------------------------------------------------------
__global__ void cumsum_kernel(const int* __restrict__ dur) {
    const int b = blockIdx.x;
    const int tid = threadIdx.x;           // 256 threads
    const int CH = 5;
    __shared__ int part[256];

    int base = tid * CH;
    int s = 0;
#pragma unroll
    for (int j = 0; j < CH; j++) {
        int p = base + j;
        if (p < TP) s += dur[b * TP + p];
    }
    part[tid] = s;
    __syncthreads();

    for (int off = 1; off < 256; off <<= 1) {
        int v = (tid >= off) ? part[tid - off] : 0;
        __syncthreads();
        part[tid] += v;
        __syncthreads();
    }

    int run = (tid > 0) ? part[tid - 1] : 0;
#pragma unroll
    for (int j = 0; j < CH; j++) {
        int p = base + j;
        if (p < TP) {
            run += dur[b * TP + p];
            g_cum[b * TP + p] = run;
        }
    }
}

// ---------------------------------------------------------------------------
// tf32 tensor-core duration predictor.
// grid = (BB, 4 groups, NCHUNK t-chunks); block = 384 = 12 warps.
// Warp w = n-tile w (8 output channels of this group); B held in 72 regs.
// Per m16 t-subtile: stage x[18 x 96] (tf32-rounded) -> 36 HMMA -> epilogue.
// ---------------------------------------------------------------------------
__global__ __launch_bounds__(384, 1)
void conv_mma_kernel(const float* __restrict__ ph,
                     const float* __restrict__ sil,
                     const float* __restrict__ b1,
                     const float* __restrict__ w2) {
    __shared__ unsigned int xs[18 * XS_PAD];
    __shared__ float red[16 * NWARPS];

    const int b     = blockIdx.x;
    const int g     = blockIdx.y;
    const int chunk = blockIdx.z;
    const int tid   = threadIdx.x;
    const int wid   = tid >> 5;       // n-tile
    const int lane  = tid & 31;
    const int g4    = lane >> 2;      // groupID (row within fragment)
    const int t4    = lane & 3;       // threadID-in-group (col)

    // Load this warp's B fragments (72 regs), once per block.
    unsigned int Breg0[NKS], Breg1[NKS];
    {
        const unsigned int* wb =
            g_wB + ((g * NWARPS + wid) * NKS) * 2 * 32 + lane;
#pragma unroll
        for (int ks = 0; ks < NKS; ks++) {
            Breg0[ks] = wb[(ks * 2 + 0) * 32];
            Breg1[ks] = wb[(ks * 2 + 1) * 32];
        }
    }

    // Per-thread epilogue constants: this thread's two output channels.
    const int c0 = wid * 8 + 2 * t4;
    const int C0 = g * GC + c0;
    const float w2_0 = w2[C0],     w2_1 = w2[C0 + 1];
    const float b1_0 = b1[C0],     b1_1 = b1[C0 + 1];

    for (int sub = 0; sub < SUBS; sub++) {
        const int tsub0 = chunk * (SUBS * 16) + sub * 16;
        __syncthreads();   // xs/red free from previous iteration

        // Stage x slice [18 rows x 96 ch], tf32-rounded. Row lt -> t = tsub0-1+lt.
        for (int e = tid; e < 18 * GC; e += 384) {
            int row = e / GC;
            int col = e - row * GC;
            int tg  = tsub0 - 1 + row;
            float v = 0.f;
            if ((unsigned)tg < TT_IN)  v = ph[((size_t)b * TT_IN + tg) * EMB + g * GC + col];
            else if (tg == TT_IN)      v = sil[g * GC + col];
            unsigned u; CVT_TF32(u, v);
            xs[row * XS_PAD + col] = u;
        }
        __syncthreads();

        float d0 = 0.f, d1 = 0.f, d2 = 0.f, d3 = 0.f;
#pragma unroll
        for (int kk = 0; kk < 3; kk++) {
            const unsigned int* xrow  = xs + (g4 + kk) * XS_PAD + t4;
            const unsigned int* xrow8 = xrow + 8 * XS_PAD;
#pragma unroll
            for (int ki = 0; ki < 12; ki++) {
                const int ib = ki * 8;
                unsigned a0 = xrow[ib];
                unsigned a1 = xrow8[ib];
                unsigned a2 = xrow[ib + 4];
                unsigned a3 = xrow8[ib + 4];
                MMA_TF32(d0, d1, d2, d3, a0, a1, a2, a3,
                         Breg0[kk * 12 + ki], Breg1[kk * 12 + ki]);
            }
        }

        // Epilogue: relu + b1, dot w2 for this thread's 2 channels, 2 rows.
        float pl = w2_0 * fmaxf(d0 + b1_0, 0.f) + w2_1 * fmaxf(d1 + b1_1, 0.f);
        float ph_ = w2_0 * fmaxf(d2 + b1_0, 0.f) + w2_1 * fmaxf(d3 + b1_1, 0.f);
        pl  += __shfl_xor_sync(0xffffffffu, pl, 1);
        pl  += __shfl_xor_sync(0xffffffffu, pl, 2);
        ph_ += __shfl_xor_sync(0xffffffffu, ph_, 1);
        ph_ += __shfl_xor_sync(0xffffffffu, ph_, 2);
        if (t4 == 0) {
            red[g4 * NWARPS + wid]       = pl;
            red[(g4 + 8) * NWARPS + wid] = ph_;
        }
        __syncthreads();

        if (tid < 16) {
            int t = tsub0 + tid;
            if (t < TP) {
                float s = 0.f;
#pragma unroll
                for (int w = 0; w < NWARPS; w++) s += red[tid * NWARPS + w];
                g_part[(g * BB + b) * TP + t] = s;
            }
        }
    }
}

// Sum 4 group partials + b2 -> durations_pred (deterministic).
__global__ void pred_sum_kernel(const float* __restrict__ b2,
                                float* __restrict__ dpred) {
    int i = blockIdx.x * blockDim.x + threadIdx.x;
    if (i >= BB * TP) return;
    float s = b2[0];
#pragma unroll
    for (int g = 0; g < 4; g++) s += g_part[g * BB * TP + i];
    dpred[i] = s;
}

// ---------------------------------------------------------------------------
// Length regulation by SCATTER: one warp per (b, token j).
// ---------------------------------------------------------------------------
__global__ void scatter_kernel(const float* __restrict__ ph,
                               const float* __restrict__ sil,
                               float* __restrict__ out,
                               int t_out) {
    const int w = (blockIdx.x * blockDim.x + threadIdx.x) >> 5;
    const int lane = threadIdx.x & 31;
    if (w >= BB * TP) return;
    const int b = w / TP;
    const int j = w - b * TP;

    const int hi = g_cum[b * TP + j];
    const int lo = j ? g_cum[b * TP + j - 1] : 0;
    const int d = hi - lo;
    if (d <= 0) return;

    const float4* src = (j < TT_IN)
        ? (const float4*)(ph + ((size_t)b * TT_IN + j) * EMB)
        : (const float4*)sil;
    float4 r0 = __ldcs(src + lane);
    float4 r1 = __ldcs(src + 32 + lane);
    float4 r2 = __ldcs(src + 64 + lane);

    float4* dst = (float4*)(out + ((size_t)b * t_out + lo) * EMB);
    for (int f = 0; f < d; f++, dst += EMB / 4) {
        __stcs(dst + lane,      r0);
        __stcs(dst + 32 + lane, r1);
        __stcs(dst + 64 + lane, r2);
    }
}

// Zero-fill frames past each batch's total length (out buffer is poisoned).
__global__ void zerotail_kernel(float* __restrict__ out, int t_out) {
    const int b = blockIdx.x;
    const int tot = g_cum[b * TP + TP - 1];
    if (tot >= t_out) return;
    float4* dst = (float4*)(out + ((size_t)b * t_out + tot) * EMB);
    const int n4 = (t_out - tot) * (EMB / 4);
    const float4 z = make_float4(0.f, 0.f, 0.f, 0.f);
    for (int i = threadIdx.x; i < n4; i += blockDim.x) __stcs(dst + i, z);
}

// ---------------------------------------------------------------------------
// Launch
// ---------------------------------------------------------------------------
extern "C" void kernel_launch(void* const* d_in, const int* in_sizes, int n_in,
                              void* d_out, int out_size) {
    const float* ph  = (const float*)d_in[0];   // [32,1024,384]
    const float* sil = (const float*)d_in[1];   // [384]
    const float* w1  = (const float*)d_in[2];   // [384,96,3]
    const float* b1  = (const float*)d_in[3];   // [384]
    const float* w2  = (const float*)d_in[4];   // [1,384,1]
    const float* b2  = (const float*)d_in[5];   // [1]
    const int*   dur = (const int*)d_in[6];     // [32,1025]

    const int t_out = (out_size - BB * TP) / (BB * EMB);

    float* out_exp  = (float*)d_out;                             // [B,t_out,EMB]
    float* out_pred = (float*)d_out + (size_t)BB * t_out * EMB;  // [B,TP]

    prep_w_kernel<<<(4 * NWARPS * NKS * 32 + 255) / 256, 256>>>(w1);
    cumsum_kernel<<<BB, 256>>>(dur);

    dim3 cgrid(BB, 4, NCHUNK);
    conv_mma_kernel<<<cgrid, 384>>>(ph, sil, b1, w2);
    pred_sum_kernel<<<(BB * TP + 255) / 256, 256>>>(b2, out_pred);

    const int warps = BB * TP;
    scatter_kernel<<<(warps * 32 + 255) / 256, 256>>>(ph, sil, out_exp, t_out);
    zerotail_kernel<<<BB, 256>>>(out_exp, t_out);
}

// round 5
// speedup vs baseline: 1.2365x; 1.2365x over previous
#include <cuda_runtime.h>

#define BB 32
#define TT_IN 1024
#define TP 1025
#define EMB 384
#define GC 96
#define NI4 24           // GC/4 input-channel quads
#define NWARPS 12
#define CTILE 16         // time steps per conv block
#define XROWS (CTILE + 2)

// Scratch (device globals: no allocations allowed)
__device__ int        g_cum[BB * TP];
__device__ ulonglong2 g_wt4[3 * NI4 * EMB];  // [k][i4][c]: 4 floats = w[c][4i4..4i4+3][k]

// Packed fp32x2 FMA (Blackwell): d.lo+=a.lo*b.lo ; d.hi+=a.hi*b.hi
#define FFMA2(acc, a, b) \
    asm("fma.rn.f32x2 %0, %1, %2, %0;" : "+l"(acc) : "l"(a), "l"(b))

// ---------------------------------------------------------------------------
// Pack conv1 weights [c][i][k] -> float4 quads [k][i4][c]
// ---------------------------------------------------------------------------
__global__ void transpose_w_kernel(const float* __restrict__ w1) {
    int idx = blockIdx.x * blockDim.x + threadIdx.x;
    if (idx >= 3 * NI4 * EMB) return;
    int c  = idx % EMB;
    int i4 = (idx / EMB) % NI4;
    int k  = idx / (EMB * NI4);
    float4 p;
    p.x = w1[c * (GC * 3) + (4 * i4 + 0) * 3 + k];
    p.y = w1[c * (GC * 3) + (4 * i4 + 1) * 3 + k];
    p.z = w1[c * (GC * 3) + (4 * i4 + 2) * 3 + k];
    p.w = w1[c * (GC * 3) + (4 * i4 + 3) * 3 + k];
    g_wt4[idx] = *(ulonglong2*)&p;
}

// ---------------------------------------------------------------------------
// Inclusive cumsum of durations per batch row (one block per b)
// ---------------------------------------------------------------------------
__global__ void cumsum_kernel(const int* __restrict__ dur) {
    const int b = blockIdx.x;
    const int tid = threadIdx.x;           // 256 threads
    const int CH = 5;                      // 256*5 = 1280 >= 1025
    __shared__ int part[256];

    int base = tid * CH;
    int s = 0;
#pragma unroll
    for (int j = 0; j < CH; j++) {
        int p = base + j;
        if (p < TP) s += dur[b * TP + p];
    }
    part[tid] = s;
    __syncthreads();

    for (int off = 1; off < 256; off <<= 1) {
        int v = (tid >= off) ? part[tid - off] : 0;
        __syncthreads();
        part[tid] += v;
        __syncthreads();
    }

    int run = (tid > 0) ? part[tid - 1] : 0;
#pragma unroll
    for (int j = 0; j < CH; j++) {
        int p = base + j;
        if (p < TP) {
            run += dur[b * TP + p];
            g_cum[b * TP + p] = run;
        }
    }
}

// ---------------------------------------------------------------------------
// Fused duration predictor, f32x2-packed, 4-channel quads, CTILE=16, occ 2.
// Scatter-form inner loop: each x row position loaded exactly once (LDS.128
// broadcast), contributing to acc[lt], acc[lt-1], acc[lt-2] with w_k quads.
// ---------------------------------------------------------------------------
__global__ __launch_bounds__(384, 2)
void conv_kernel(const float* __restrict__ ph,
                 const float* __restrict__ sil,
                 const float* __restrict__ b1,
                 const float* __restrict__ w2,
                 const float* __restrict__ b2,
                 float* __restrict__ dpred) {
    __shared__ float xs[XROWS * EMB];      // [t][c]
    __shared__ float red[NWARPS * CTILE];

    const int b   = blockIdx.y;
    const int t0  = blockIdx.x * CTILE;
    const int tid = threadIdx.x;           // output channel c

    // Stage x tile [t][c]: global t = t0-1+lt; t==1024 -> silence; else zero.
#pragma unroll
    for (int lt = 0; lt < XROWS; lt++) {
        int tg = t0 - 1 + lt;
        float v = 0.f;
        if ((unsigned)tg < TT_IN)  v = ph[((size_t)b * TT_IN + tg) * EMB + tid];
        else if (tg == TT_IN)      v = sil[tid];
        xs[lt * EMB + tid] = v;
    }
    __syncthreads();

    const int cbase = (tid / GC) * GC;     // group channel base

    unsigned long long acc[CTILE];
#pragma unroll
    for (int t = 0; t < CTILE; t++) acc[t] = 0ULL;

    const ulonglong2* wq = g_wt4 + tid;

    for (int i4 = 0; i4 < NI4; i4++) {
        ulonglong2 w0 = wq[(0 * NI4 + i4) * EMB];
        ulonglong2 w1 = wq[(1 * NI4 + i4) * EMB];
        ulonglong2 w2q = wq[(2 * NI4 + i4) * EMB];

        const ulonglong2* xq =
            (const ulonglong2*)(xs + cbase + 4 * i4);   // row stride EMB floats
#pragma unroll
        for (int lt = 0; lt < XROWS; lt++) {
            ulonglong2 x = xq[lt * (EMB / 4)];
            if (lt < CTILE)                 { FFMA2(acc[lt],     w0.x,  x.x); FFMA2(acc[lt],     w0.y,  x.y); }
            if (lt >= 1 && lt - 1 < CTILE)  { FFMA2(acc[lt - 1], w1.x,  x.x); FFMA2(acc[lt - 1], w1.y,  x.y); }
            if (lt >= 2)                    { FFMA2(acc[lt - 2], w2q.x, x.x); FFMA2(acc[lt - 2], w2q.y, x.y); }
        }
    }

    // Epilogue: lo+hi+bias, ReLU, * w2[c], reduce over 384 channels.
    const float bias = b1[tid];
    const float w2c  = w2[tid];
    const int lane = tid & 31;
    const int warp = tid >> 5;
#pragma unroll
    for (int t = 0; t < CTILE; t++) {
        unsigned lo, hi;
        asm("mov.b64 {%0,%1}, %2;" : "=r"(lo), "=r"(hi) : "l"(acc[t]));
        float v = __uint_as_float(lo) + __uint_as_float(hi) + bias;
        v = w2c * fmaxf(v, 0.f);
        v += __shfl_down_sync(0xffffffffu, v, 16);
        v += __shfl_down_sync(0xffffffffu, v, 8);
        v += __shfl_down_sync(0xffffffffu, v, 4);
        v += __shfl_down_sync(0xffffffffu, v, 2);
        v += __shfl_down_sync(0xffffffffu, v, 1);
        if (lane == 0) red[warp * CTILE + t] = v;
    }
    __syncthreads();

    if (tid < CTILE) {
        int t = t0 + tid;
        if (t < TP) {
            float s = b2[0];
#pragma unroll
            for (int w = 0; w < NWARPS; w++) s += red[w * CTILE + tid];
            dpred[b * TP + t] = s;
        }
    }
}

// ---------------------------------------------------------------------------
// Length regulation by SCATTER: one warp per (b, token j).
// ---------------------------------------------------------------------------
__global__ void scatter_kernel(const float* __restrict__ ph,
                               const float* __restrict__ sil,
                               float* __restrict__ out,
                               int t_out) {
    const int w = (blockIdx.x * blockDim.x + threadIdx.x) >> 5;
    const int lane = threadIdx.x & 31;
    if (w >= BB * TP) return;
    const int b = w / TP;
    const int j = w - b * TP;

    const int hi = g_cum[b * TP + j];
    const int lo = j ? g_cum[b * TP + j - 1] : 0;
    const int d = hi - lo;
    if (d <= 0) return;

    const float4* src = (j < TT_IN)
        ? (const float4*)(ph + ((size_t)b * TT_IN + j) * EMB)
        : (const float4*)sil;
    float4 r0 = __ldcs(src + lane);
    float4 r1 = __ldcs(src + 32 + lane);
    float4 r2 = __ldcs(src + 64 + lane);

    float4* dst = (float4*)(out + ((size_t)b * t_out + lo) * EMB);
    for (int f = 0; f < d; f++, dst += EMB / 4) {
        __stcs(dst + lane,      r0);
        __stcs(dst + 32 + lane, r1);
        __stcs(dst + 64 + lane, r2);
    }
}

// Zero-fill frames past each batch's total length (out buffer is poisoned).
__global__ void zerotail_kernel(float* __restrict__ out, int t_out) {
    const int b = blockIdx.x;
    const int tot = g_cum[b * TP + TP - 1];
    if (tot >= t_out) return;
    float4* dst = (float4*)(out + ((size_t)b * t_out + tot) * EMB);
    const int n4 = (t_out - tot) * (EMB / 4);
    const float4 z = make_float4(0.f, 0.f, 0.f, 0.f);
    for (int i = threadIdx.x; i < n4; i += blockDim.x) __stcs(dst + i, z);
}

// ---------------------------------------------------------------------------
// Launch
// ---------------------------------------------------------------------------
extern "C" void kernel_launch(void* const* d_in, const int* in_sizes, int n_in,
                              void* d_out, int out_size) {
    const float* ph  = (const float*)d_in[0];   // [32,1024,384]
    const float* sil = (const float*)d_in[1];   // [384]
    const float* w1  = (const float*)d_in[2];   // [384,96,3]
    const float* b1  = (const float*)d_in[3];   // [384]
    const float* w2  = (const float*)d_in[4];   // [1,384,1]
    const float* b2  = (const float*)d_in[5];   // [1]
    const int*   dur = (const int*)d_in[6];     // [32,1025]

    const int t_out = (out_size - BB * TP) / (BB * EMB);

    float* out_exp  = (float*)d_out;                             // [B,t_out,EMB]
    float* out_pred = (float*)d_out + (size_t)BB * t_out * EMB;  // [B,TP]

    transpose_w_kernel<<<(3 * NI4 * EMB + 255) / 256, 256>>>(w1);
    cumsum_kernel<<<BB, 256>>>(dur);

    dim3 cgrid((TP + CTILE - 1) / CTILE, BB);
    conv_kernel<<<cgrid, EMB>>>(ph, sil, b1, w2, b2, out_pred);

    const int warps = BB * TP;
    scatter_kernel<<<(warps * 32 + 255) / 256, 256>>>(ph, sil, out_exp, t_out);
    zerotail_kernel<<<BB, 256>>>(out_exp, t_out);
}